// round 3
// baseline (speedup 1.0000x reference)
#include <cuda_runtime.h>

#define BATCH   8
#define NPTS    4096
#define NBD     16          // batch * 2 directions
#define QCHUNK  256         // queries per block
#define NQC     16          // 4096 / 256
#define THALF   2048        // targets per block (half of 4096)
#define NTH     2
#define THREADS 128
#define QPT     2           // queries per thread

// Per-query partial mins: [bd][query][target_half]
__device__ float g_pmins[NBD * NPTS * 2];

// ---- packed f32x2 helpers (sm_100+; FFMA2 reachable only via PTX) ----
__device__ __forceinline__ double pack2(float lo, float hi) {
    double d;
    asm("mov.b64 %0, {%1, %2};" : "=d"(d) : "f"(lo), "f"(hi));
    return d;
}
__device__ __forceinline__ double fma2(double a, double b, double c) {
    double d;
    asm("fma.rn.f32x2 %0, %1, %2, %3;" : "=d"(d) : "d"(a), "d"(b), "d"(c));
    return d;
}
__device__ __forceinline__ void unpack2(double d, float& lo, float& hi) {
    asm("mov.b64 {%0, %1}, %2;" : "=f"(lo), "=f"(hi) : "d"(d));
}

// Stage 1: each block = (batch*dir, query-chunk, target-half).
// Loads its 2048-target tile into SMEM as SoA (x,y,z,t2), then each thread
// scans the tile for its 2 queries using packed f32x2 FMA:
//   d = t2 - 2*q.t   (add q^2 at the end; argmin unchanged)
__global__ __launch_bounds__(THREADS)
void chamfer_stage1(const float* __restrict__ x, const float* __restrict__ y) {
    __shared__ __align__(16) float sx[THALF];
    __shared__ __align__(16) float sy[THALF];
    __shared__ __align__(16) float sz[THALF];
    __shared__ __align__(16) float s2[THALF];

    const int blk = blockIdx.x;
    const int th  = blk & 1;          // target half
    const int qc  = (blk >> 1) & 15;  // query chunk
    const int bd  = blk >> 5;         // batch*2 + dir, 0..15
    const int b   = bd >> 1;
    const int dir = bd & 1;

    // dir 0: query = x, target = y  (min over axis=2)
    // dir 1: query = y, target = x  (min over axis=1)
    const float* __restrict__ q = (dir ? y : x) + b * NPTS * 3;
    const float* __restrict__ t = (dir ? x : y) + b * NPTS * 3;

    const int t0 = th * THALF;
    for (int i = threadIdx.x; i < THALF; i += THREADS) {
        const float tx = t[(t0 + i) * 3 + 0];
        const float ty = t[(t0 + i) * 3 + 1];
        const float tz = t[(t0 + i) * 3 + 2];
        sx[i] = tx; sy[i] = ty; sz[i] = tz;
        s2[i] = tx * tx + ty * ty + tz * tz;
    }
    __syncthreads();

    const int q0 = qc * QCHUNK + threadIdx.x;
    const int q1 = q0 + THREADS;

    const float ax0 = q[q0 * 3 + 0], ay0 = q[q0 * 3 + 1], az0 = q[q0 * 3 + 2];
    const float ax1 = q[q1 * 3 + 0], ay1 = q[q1 * 3 + 1], az1 = q[q1 * 3 + 2];
    const float qsq0 = ax0 * ax0 + ay0 * ay0 + az0 * az0;
    const float qsq1 = ax1 * ax1 + ay1 * ay1 + az1 * az1;

    // broadcast-packed -2*q coefficients (loop invariant)
    const double pAx = pack2(-2.f * ax0, -2.f * ax0);
    const double pAy = pack2(-2.f * ay0, -2.f * ay0);
    const double pAz = pack2(-2.f * az0, -2.f * az0);
    const double pBx = pack2(-2.f * ax1, -2.f * ax1);
    const double pBy = pack2(-2.f * ay1, -2.f * ay1);
    const double pBz = pack2(-2.f * az1, -2.f * az1);

    // 4 independent min accumulators per query -> FMNMX chain = 512*4 cyc
    float mAa = 1e30f, mAb = 1e30f, mAc = 1e30f, mAd = 1e30f;
    float mBa = 1e30f, mBb = 1e30f, mBc = 1e30f, mBd = 1e30f;

    const double2* __restrict__ px = (const double2*)sx;
    const double2* __restrict__ py = (const double2*)sy;
    const double2* __restrict__ pz = (const double2*)sz;
    const double2* __restrict__ p2 = (const double2*)s2;

#pragma unroll 4
    for (int k = 0; k < THALF / 4; k++) {
        const double2 vx = px[k];   // {t0x,t1x},{t2x,t3x} bit-packed pairs
        const double2 vy = py[k];
        const double2 vz = pz[k];
        const double2 v2 = p2[k];

        const double dA0 = fma2(pAx, vx.x, fma2(pAy, vy.x, fma2(pAz, vz.x, v2.x)));
        const double dA1 = fma2(pAx, vx.y, fma2(pAy, vy.y, fma2(pAz, vz.y, v2.y)));
        const double dB0 = fma2(pBx, vx.x, fma2(pBy, vy.x, fma2(pBz, vz.x, v2.x)));
        const double dB1 = fma2(pBx, vx.y, fma2(pBy, vy.y, fma2(pBz, vz.y, v2.y)));

        float f0, f1;
        unpack2(dA0, f0, f1); mAa = fminf(mAa, f0); mAb = fminf(mAb, f1);
        unpack2(dA1, f0, f1); mAc = fminf(mAc, f0); mAd = fminf(mAd, f1);
        unpack2(dB0, f0, f1); mBa = fminf(mBa, f0); mBb = fminf(mBb, f1);
        unpack2(dB1, f0, f1); mBc = fminf(mBc, f0); mBd = fminf(mBd, f1);
    }

    const float mA = fminf(fminf(mAa, mAb), fminf(mAc, mAd)) + qsq0;
    const float mB = fminf(fminf(mBa, mBb), fminf(mBc, mBd)) + qsq1;

    g_pmins[(bd * NPTS + q0) * 2 + th] = mA;
    g_pmins[(bd * NPTS + q1) * 2 + th] = mB;
}

// Stage 2: min-combine the two target halves per query, deterministic sum,
// scale: loss = sum * 0.005 / 32768  (each direction's mean is over 8*4096)
__global__ void chamfer_stage2(float* __restrict__ out) {
    __shared__ float ssum[32];
    float local = 0.f;
    const float2* __restrict__ p = (const float2*)g_pmins;
    for (int j = threadIdx.x; j < NBD * NPTS; j += blockDim.x) {
        const float2 v = p[j];
        local += fminf(v.x, v.y);
    }
#pragma unroll
    for (int o = 16; o; o >>= 1) local += __shfl_down_sync(0xFFFFFFFFu, local, o);
    if ((threadIdx.x & 31) == 0) ssum[threadIdx.x >> 5] = local;
    __syncthreads();
    if (threadIdx.x < 32) {
        float v = (threadIdx.x < (blockDim.x >> 5)) ? ssum[threadIdx.x] : 0.f;
#pragma unroll
        for (int o = 16; o; o >>= 1) v += __shfl_down_sync(0xFFFFFFFFu, v, o);
        if (threadIdx.x == 0) out[0] = v * (0.005f / 32768.f);
    }
}

extern "C" void kernel_launch(void* const* d_in, const int* in_sizes, int n_in,
                              void* d_out, int out_size) {
    const float* x = (const float*)d_in[0];
    const float* y = (const float*)d_in[1];
    float* out = (float*)d_out;
    chamfer_stage1<<<NBD * NQC * NTH, THREADS>>>(x, y);
    chamfer_stage2<<<1, 1024>>>(out);
}

// round 4
// speedup vs baseline: 1.1476x; 1.1476x over previous
#include <cuda_runtime.h>

#define NPTS    4096
#define NBD     16          // batch * 2 directions
#define QCHUNK  256         // queries per block
#define NQC     16          // 4096 / 256
#define THREADS 128
#define SMEM_BYTES (4 * NPTS * 4)   // 64 KB: sx, sy, sz, s2 planes

// Per-block partial sums (256 blocks)
__device__ float g_part[NBD * NQC];

// ---- packed f32x2 helpers ----
__device__ __forceinline__ double pack2(float lo, float hi) {
    double d;
    asm("mov.b64 %0, {%1, %2};" : "=d"(d) : "f"(lo), "f"(hi));
    return d;
}
__device__ __forceinline__ double fma2(double a, double b, double c) {
    double d;
    asm("fma.rn.f32x2 %0, %1, %2, %3;" : "=d"(d) : "d"(a), "d"(b), "d"(c));
    return d;
}
__device__ __forceinline__ void unpack2(double d, float& lo, float& hi) {
    asm("mov.b64 {%0, %1}, %2;" : "=f"(lo), "=f"(hi) : "d"(d));
}
// Load two 64-bit packed-float pairs straight from shared memory into pair
// registers (no float4 -> pair shuffling possible).
__device__ __forceinline__ void lds_v2b64(double& a, double& b, unsigned addr) {
    asm volatile("ld.shared.v2.b64 {%0, %1}, [%2];"
                 : "=d"(a), "=d"(b) : "r"(addr));
}

// Stage 1: block = (bd, query-chunk). Full 4096-target tile in SMEM as SoA
// (x, y, z, |t|^2). Each thread scans the tile for 2 queries:
//   d = t2 + (-2qx)*tx + (-2qy)*ty + (-2qz)*tz ; true dist = d + |q|^2
// using packed fma.rn.f32x2 (2 targets per instruction). Block then reduces
// its 256 query-mins (+|q|^2) to one partial sum.
__global__ __launch_bounds__(THREADS)
void chamfer_stage1(const float* __restrict__ x, const float* __restrict__ y) {
    extern __shared__ __align__(16) float smem[];
    float* sx = smem;
    float* sy = smem + NPTS;
    float* sz = smem + 2 * NPTS;
    float* s2 = smem + 3 * NPTS;

    const int blk = blockIdx.x;
    const int qc  = blk & 15;
    const int bd  = blk >> 4;       // 0..15
    const int b   = bd >> 1;
    const int dir = bd & 1;

    const float* __restrict__ q = (dir ? y : x) + b * NPTS * 3;
    const float* __restrict__ t = (dir ? x : y) + b * NPTS * 3;

    for (int i = threadIdx.x; i < NPTS; i += THREADS) {
        const float tx = t[i * 3 + 0];
        const float ty = t[i * 3 + 1];
        const float tz = t[i * 3 + 2];
        sx[i] = tx; sy[i] = ty; sz[i] = tz;
        s2[i] = tx * tx + ty * ty + tz * tz;
    }
    __syncthreads();

    const int q0 = qc * QCHUNK + threadIdx.x;
    const int q1 = q0 + THREADS;

    const float ax0 = q[q0 * 3 + 0], ay0 = q[q0 * 3 + 1], az0 = q[q0 * 3 + 2];
    const float ax1 = q[q1 * 3 + 0], ay1 = q[q1 * 3 + 1], az1 = q[q1 * 3 + 2];
    const float qsq0 = ax0 * ax0 + ay0 * ay0 + az0 * az0;
    const float qsq1 = ax1 * ax1 + ay1 * ay1 + az1 * az1;

    const double pAx = pack2(-2.f * ax0, -2.f * ax0);
    const double pAy = pack2(-2.f * ay0, -2.f * ay0);
    const double pAz = pack2(-2.f * az0, -2.f * az0);
    const double pBx = pack2(-2.f * ax1, -2.f * ax1);
    const double pBy = pack2(-2.f * ay1, -2.f * ay1);
    const double pBz = pack2(-2.f * az1, -2.f * az1);

    float mAa = 1e30f, mAb = 1e30f, mAc = 1e30f, mAd = 1e30f;
    float mBa = 1e30f, mBb = 1e30f, mBc = 1e30f, mBd = 1e30f;

    // shared-space byte address of sx; planes at +16K/+32K/+48K immediates
    unsigned a = (unsigned)__cvta_generic_to_shared(sx);

#pragma unroll 8
    for (int k = 0; k < NPTS / 4; k++, a += 16) {
        double x01, x23, y01, y23, z01, z23, w01, w23;
        lds_v2b64(x01, x23, a);
        lds_v2b64(y01, y23, a + 16384u);
        lds_v2b64(z01, z23, a + 32768u);
        lds_v2b64(w01, w23, a + 49152u);

        const double dA0 = fma2(pAx, x01, fma2(pAy, y01, fma2(pAz, z01, w01)));
        const double dA1 = fma2(pAx, x23, fma2(pAy, y23, fma2(pAz, z23, w23)));
        const double dB0 = fma2(pBx, x01, fma2(pBy, y01, fma2(pBz, z01, w01)));
        const double dB1 = fma2(pBx, x23, fma2(pBy, y23, fma2(pBz, z23, w23)));

        float f0, f1;
        unpack2(dA0, f0, f1); mAa = fminf(mAa, f0); mAb = fminf(mAb, f1);
        unpack2(dA1, f0, f1); mAc = fminf(mAc, f0); mAd = fminf(mAd, f1);
        unpack2(dB0, f0, f1); mBa = fminf(mBa, f0); mBb = fminf(mBb, f1);
        unpack2(dB1, f0, f1); mBc = fminf(mBc, f0); mBd = fminf(mBd, f1);
    }

    const float mA = fminf(fminf(mAa, mAb), fminf(mAc, mAd)) + qsq0;
    const float mB = fminf(fminf(mBa, mBb), fminf(mBc, mBd)) + qsq1;

    // deterministic block-sum of 256 query mins
    __shared__ float red[4];
    float local = mA + mB;
#pragma unroll
    for (int o = 16; o; o >>= 1) local += __shfl_down_sync(0xFFFFFFFFu, local, o);
    if ((threadIdx.x & 31) == 0) red[threadIdx.x >> 5] = local;
    __syncthreads();
    if (threadIdx.x == 0)
        g_part[blk] = (red[0] + red[1]) + (red[2] + red[3]);
}

// Stage 2: sum 256 partials, scale: loss = sum * 0.005 / 32768
__global__ void chamfer_stage2(float* __restrict__ out) {
    __shared__ float red[8];
    float v = g_part[threadIdx.x];
#pragma unroll
    for (int o = 16; o; o >>= 1) v += __shfl_down_sync(0xFFFFFFFFu, v, o);
    if ((threadIdx.x & 31) == 0) red[threadIdx.x >> 5] = v;
    __syncthreads();
    if (threadIdx.x == 0) {
        float s = ((red[0] + red[1]) + (red[2] + red[3]))
                + ((red[4] + red[5]) + (red[6] + red[7]));
        out[0] = s * (0.005f / 32768.f);
    }
}

extern "C" void kernel_launch(void* const* d_in, const int* in_sizes, int n_in,
                              void* d_out, int out_size) {
    const float* x = (const float*)d_in[0];
    const float* y = (const float*)d_in[1];
    float* out = (float*)d_out;
    cudaFuncSetAttribute(chamfer_stage1,
                         cudaFuncAttributeMaxDynamicSharedMemorySize, SMEM_BYTES);
    chamfer_stage1<<<NBD * NQC, THREADS, SMEM_BYTES>>>(x, y);
    chamfer_stage2<<<1, 256>>>(out);
}

// round 5
// speedup vs baseline: 1.2367x; 1.0776x over previous
#include <cuda_runtime.h>

#define NPTS    4096
#define NB      8
#define NIC     16        // i-chunks of 256 queries
#define NJH     4         // j-segments of 1024 targets
#define JSEG    1024
#define THREADS 128
#define NPART   64        // ic*4 + warp
#define BIAS    128.0f

// stage1 -> stage2 partials (static device arrays: allocation-free)
__device__ float g_colpart[NB * NPART * NPTS];   // [b][part][j], 8.4 MB
__device__ float g_rowpart[NB * NPTS * NJH];     // [b][i][jh]
__device__ float g_final[96];

// ---- packed f32x2 + redux helpers ----
__device__ __forceinline__ double pack2(float lo, float hi) {
    double d; asm("mov.b64 %0, {%1, %2};" : "=d"(d) : "f"(lo), "f"(hi)); return d;
}
__device__ __forceinline__ double fma2(double a, double b, double c) {
    double d; asm("fma.rn.f32x2 %0, %1, %2, %3;" : "=d"(d) : "d"(a), "d"(b), "d"(c)); return d;
}
__device__ __forceinline__ double add2(double a, double b) {
    double d; asm("add.rn.f32x2 %0, %1, %2;" : "=d"(d) : "d"(a), "d"(b)); return d;
}
__device__ __forceinline__ void unpack2(double d, float& lo, float& hi) {
    asm("mov.b64 {%0, %1}, %2;" : "=f"(lo), "=f"(hi) : "d"(d));
}
__device__ __forceinline__ void lds_v2b64(double& a, double& b, unsigned addr) {
    asm volatile("ld.shared.v2.b64 {%0, %1}, [%2];" : "=d"(a), "=d"(b) : "r"(addr));
}
__device__ __forceinline__ unsigned redux_min_u32(unsigned v) {
    unsigned r; asm("redux.sync.min.u32 %0, %1, 0xffffffff;" : "=r"(r) : "r"(v)); return r;
}

// Stage 1: block = (b, i-chunk of 256, j-segment of 1024). Computes the full
// pdist tile ONCE, biased: d''' = |x_i - y_j|^2 + 128 (> 0 always), via
//   d''' = (-2qx)tx + (-2qy)ty + (-2qz)tz + (t^2+128) + q^2
// Row mins (over j) accumulate in registers per thread (2 queries/thread).
// Col mins (over i) use redux.sync.min.u32 per (warp, j) -> per-part gmem.
__global__ __launch_bounds__(THREADS)
void chamfer_stage1(const float* __restrict__ x, const float* __restrict__ y) {
    __shared__ __align__(16) float sm[4 * JSEG];   // planes: tx, ty, tz, t^2+128

    const int blk = blockIdx.x;
    const int jh  = blk & 3;
    const int ic  = (blk >> 2) & 15;
    const int b   = blk >> 6;

    const float* __restrict__ q = x + b * NPTS * 3;
    const float* __restrict__ t = y + b * NPTS * 3;
    const int j0 = jh * JSEG;

    for (int i = threadIdx.x; i < JSEG; i += THREADS) {
        const float tx = t[(j0 + i) * 3 + 0];
        const float ty = t[(j0 + i) * 3 + 1];
        const float tz = t[(j0 + i) * 3 + 2];
        sm[i] = tx; sm[JSEG + i] = ty; sm[2 * JSEG + i] = tz;
        sm[3 * JSEG + i] = tx * tx + ty * ty + tz * tz + BIAS;
    }
    __syncthreads();

    const int i1 = ic * 256 + threadIdx.x;
    const int i2 = i1 + THREADS;
    const float ax = q[i1 * 3 + 0], ay = q[i1 * 3 + 1], az = q[i1 * 3 + 2];
    const float bx = q[i2 * 3 + 0], by = q[i2 * 3 + 1], bz = q[i2 * 3 + 2];

    const double pAx = pack2(-2.f * ax, -2.f * ax);
    const double pAy = pack2(-2.f * ay, -2.f * ay);
    const double pAz = pack2(-2.f * az, -2.f * az);
    const double pBx = pack2(-2.f * bx, -2.f * bx);
    const double pBy = pack2(-2.f * by, -2.f * by);
    const double pBz = pack2(-2.f * bz, -2.f * bz);
    const float qsqA = ax * ax + ay * ay + az * az;
    const float qsqB = bx * bx + by * by + bz * bz;
    const double pQA = pack2(qsqA, qsqA);
    const double pQB = pack2(qsqB, qsqB);

    float rA0 = 1e30f, rA1 = 1e30f, rA2 = 1e30f, rA3 = 1e30f;
    float rB0 = 1e30f, rB1 = 1e30f, rB2 = 1e30f, rB3 = 1e30f;

    const int wid = threadIdx.x >> 5;
    const bool lane0 = (threadIdx.x & 31) == 0;
    float4* __restrict__ colout =
        (float4*)&g_colpart[(b * NPART + ic * 4 + wid) * NPTS + j0];

    unsigned a = (unsigned)__cvta_generic_to_shared(sm);

#pragma unroll 4
    for (int k = 0; k < JSEG / 4; k++, a += 16) {
        double x01, x23, y01, y23, z01, z23, w01, w23;
        lds_v2b64(x01, x23, a);
        lds_v2b64(y01, y23, a + 4096u);
        lds_v2b64(z01, z23, a + 8192u);
        lds_v2b64(w01, w23, a + 12288u);

        const double tA01 = add2(w01, pQA), tA23 = add2(w23, pQA);
        const double tB01 = add2(w01, pQB), tB23 = add2(w23, pQB);

        const double dA0 = fma2(pAx, x01, fma2(pAy, y01, fma2(pAz, z01, tA01)));
        const double dA1 = fma2(pAx, x23, fma2(pAy, y23, fma2(pAz, z23, tA23)));
        const double dB0 = fma2(pBx, x01, fma2(pBy, y01, fma2(pBz, z01, tB01)));
        const double dB1 = fma2(pBx, x23, fma2(pBy, y23, fma2(pBz, z23, tB23)));

        float a0, a1, a2, a3, b0, b1, b2, b3;
        unpack2(dA0, a0, a1); unpack2(dA1, a2, a3);
        unpack2(dB0, b0, b1); unpack2(dB1, b2, b3);

        rA0 = fminf(rA0, a0); rA1 = fminf(rA1, a1);
        rA2 = fminf(rA2, a2); rA3 = fminf(rA3, a3);
        rB0 = fminf(rB0, b0); rB1 = fminf(rB1, b1);
        rB2 = fminf(rB2, b2); rB3 = fminf(rB3, b3);

        // col mins (over the 64 i's this warp holds), exact: d''' > 0 so
        // u32 min on the bit pattern == float min
        const unsigned c0 = redux_min_u32(__float_as_uint(fminf(a0, b0)));
        const unsigned c1 = redux_min_u32(__float_as_uint(fminf(a1, b1)));
        const unsigned c2 = redux_min_u32(__float_as_uint(fminf(a2, b2)));
        const unsigned c3 = redux_min_u32(__float_as_uint(fminf(a3, b3)));
        if (lane0)
            colout[k] = make_float4(__uint_as_float(c0), __uint_as_float(c1),
                                    __uint_as_float(c2), __uint_as_float(c3));
    }

    const float rowA = fminf(fminf(rA0, rA1), fminf(rA2, rA3));
    const float rowB = fminf(fminf(rB0, rB1), fminf(rB2, rB3));
    g_rowpart[(b * NPTS + i1) * NJH + jh] = rowA;
    g_rowpart[(b * NPTS + i2) * NJH + jh] = rowB;
}

__device__ __forceinline__ void block_sum_to(float local, int slot) {
    __shared__ float red[8];
#pragma unroll
    for (int o = 16; o; o >>= 1) local += __shfl_down_sync(0xFFFFFFFFu, local, o);
    if ((threadIdx.x & 31) == 0) red[threadIdx.x >> 5] = local;
    __syncthreads();
    if (threadIdx.x == 0) {
        float s = ((red[0] + red[1]) + (red[2] + red[3]))
                + ((red[4] + red[5]) + (red[6] + red[7]));
        g_final[slot] = s;
    }
}

// Stage 2: blocks 0..63 = col side (b, j-slice of 512): min over 64 parts,
// unbias, sum. Blocks 64..71 = row side (b): min over 4 jh, unbias, sum.
__global__ __launch_bounds__(256)
void chamfer_stage2() {
    float local = 0.f;
    if (blockIdx.x < 64) {
        const int b = blockIdx.x >> 3;
        const int j = (blockIdx.x & 7) * 512 + threadIdx.x;   // +0, +256
        float m0 = 1e30f, m1 = 1e30f;
        const float* base = &g_colpart[b * NPART * NPTS];
#pragma unroll 8
        for (int p = 0; p < NPART; p++) {
            m0 = fminf(m0, base[p * NPTS + j]);
            m1 = fminf(m1, base[p * NPTS + j + 256]);
        }
        local = (m0 - BIAS) + (m1 - BIAS);
    } else {
        const int b = blockIdx.x - 64;
        for (int i = threadIdx.x; i < NPTS; i += 256) {
            const float4 v = *(const float4*)&g_rowpart[(b * NPTS + i) * NJH];
            local += fminf(fminf(v.x, v.y), fminf(v.z, v.w)) - BIAS;
        }
    }
    block_sum_to(local, blockIdx.x);
}

// Stage 3: sum the 72 partials, scale: loss = sum * 0.005 / 32768
__global__ void chamfer_stage3(float* __restrict__ out) {
    __shared__ float red[4];
    float v = (threadIdx.x < 72) ? g_final[threadIdx.x] : 0.f;
#pragma unroll
    for (int o = 16; o; o >>= 1) v += __shfl_down_sync(0xFFFFFFFFu, v, o);
    if ((threadIdx.x & 31) == 0) red[threadIdx.x >> 5] = v;
    __syncthreads();
    if (threadIdx.x == 0) {
        float s = (red[0] + red[1]) + (red[2] + red[3]);
        out[0] = s * (0.005f / 32768.f);
    }
}

extern "C" void kernel_launch(void* const* d_in, const int* in_sizes, int n_in,
                              void* d_out, int out_size) {
    const float* x = (const float*)d_in[0];
    const float* y = (const float*)d_in[1];
    float* out = (float*)d_out;
    chamfer_stage1<<<NB * NIC * NJH, THREADS>>>(x, y);
    chamfer_stage2<<<72, 256>>>();
    chamfer_stage3<<<1, 128>>>(out);
}

// round 6
// speedup vs baseline: 1.3674x; 1.1057x over previous
#include <cuda_runtime.h>

#define NPTS    4096
#define NB      8
#define NIC     8         // i-chunks of 512 queries
#define NJH     8         // j-segments of 512 targets
#define JSEG    512
#define THREADS 256
#define NPART   64        // ic*8 + warp  (64 i's per warp-part)
#define BIAS    128.0f

// stage1 -> stage2 partials (static device arrays: allocation-free)
__device__ float g_colpart[NB * NPART * NPTS];   // [b][part][j], 8.4 MB
__device__ float g_rowpart[NB * NPTS * NJH];     // [b][i][jh],   1 MB
__device__ float g_final[96];

// ---- packed f32x2 + redux helpers ----
__device__ __forceinline__ double pack2(float lo, float hi) {
    double d; asm("mov.b64 %0, {%1, %2};" : "=d"(d) : "f"(lo), "f"(hi)); return d;
}
__device__ __forceinline__ double fma2(double a, double b, double c) {
    double d; asm("fma.rn.f32x2 %0, %1, %2, %3;" : "=d"(d) : "d"(a), "d"(b), "d"(c)); return d;
}
__device__ __forceinline__ double add2(double a, double b) {
    double d; asm("add.rn.f32x2 %0, %1, %2;" : "=d"(d) : "d"(a), "d"(b)); return d;
}
__device__ __forceinline__ void unpack2(double d, float& lo, float& hi) {
    asm("mov.b64 {%0, %1}, %2;" : "=f"(lo), "=f"(hi) : "d"(d));
}
__device__ __forceinline__ void lds_v2b64(double& a, double& b, unsigned addr) {
    asm volatile("ld.shared.v2.b64 {%0, %1}, [%2];" : "=d"(a), "=d"(b) : "r"(addr));
}
__device__ __forceinline__ unsigned redux_min_u32(unsigned v) {
    unsigned r; asm("redux.sync.min.u32 %0, %1, 0xffffffff;" : "=r"(r) : "r"(v)); return r;
}

// Stage 1: block = (b, i-chunk of 512, j-segment of 512). Computes each pdist
// tile ONCE, biased positive: d''' = |x_i - y_j|^2 + 128, via
//   d''' = (-2qx)tx + (-2qy)ty + (-2qz)tz + ((t^2+128) + q^2)
// Row mins (over j) accumulate in registers (2 queries/thread).
// Col mins (over i) use redux.sync.min.u32 per (warp, j) -> per-part gmem.
// 8 warps/block, 512 blocks -> ~28 warps/SM for latency hiding.
__global__ __launch_bounds__(THREADS)
void chamfer_stage1(const float* __restrict__ x, const float* __restrict__ y) {
    __shared__ __align__(16) float sm[4 * JSEG];   // planes: tx, ty, tz, t^2+BIAS

    const int blk = blockIdx.x;
    const int jh  = blk & 7;
    const int ic  = (blk >> 3) & 7;
    const int b   = blk >> 6;

    const float* __restrict__ q = x + b * NPTS * 3;
    const float* __restrict__ t = y + b * NPTS * 3;
    const int j0 = jh * JSEG;

    for (int i = threadIdx.x; i < JSEG; i += THREADS) {
        const float tx = t[(j0 + i) * 3 + 0];
        const float ty = t[(j0 + i) * 3 + 1];
        const float tz = t[(j0 + i) * 3 + 2];
        sm[i] = tx; sm[JSEG + i] = ty; sm[2 * JSEG + i] = tz;
        sm[3 * JSEG + i] = tx * tx + ty * ty + tz * tz + BIAS;
    }
    __syncthreads();

    const int i1 = ic * 512 + threadIdx.x;
    const int i2 = i1 + THREADS;
    const float ax = q[i1 * 3 + 0], ay = q[i1 * 3 + 1], az = q[i1 * 3 + 2];
    const float bx = q[i2 * 3 + 0], by = q[i2 * 3 + 1], bz = q[i2 * 3 + 2];

    const double pAx = pack2(-2.f * ax, -2.f * ax);
    const double pAy = pack2(-2.f * ay, -2.f * ay);
    const double pAz = pack2(-2.f * az, -2.f * az);
    const double pBx = pack2(-2.f * bx, -2.f * bx);
    const double pBy = pack2(-2.f * by, -2.f * by);
    const double pBz = pack2(-2.f * bz, -2.f * bz);
    const float qsqA = ax * ax + ay * ay + az * az;
    const float qsqB = bx * bx + by * by + bz * bz;
    const double pQA = pack2(qsqA, qsqA);
    const double pQB = pack2(qsqB, qsqB);

    float rA0 = 1e30f, rA1 = 1e30f, rA2 = 1e30f, rA3 = 1e30f;
    float rB0 = 1e30f, rB1 = 1e30f, rB2 = 1e30f, rB3 = 1e30f;

    const int wid = threadIdx.x >> 5;
    const bool lane0 = (threadIdx.x & 31) == 0;
    float4* __restrict__ colout =
        (float4*)&g_colpart[(b * NPART + ic * 8 + wid) * NPTS + j0];

    unsigned a = (unsigned)__cvta_generic_to_shared(sm);

#pragma unroll 4
    for (int k = 0; k < JSEG / 4; k++, a += 16) {
        double x01, x23, y01, y23, z01, z23, w01, w23;
        lds_v2b64(x01, x23, a);
        lds_v2b64(y01, y23, a + 2048u);
        lds_v2b64(z01, z23, a + 4096u);
        lds_v2b64(w01, w23, a + 6144u);

        const double tA01 = add2(w01, pQA), tA23 = add2(w23, pQA);
        const double tB01 = add2(w01, pQB), tB23 = add2(w23, pQB);

        const double dA0 = fma2(pAx, x01, fma2(pAy, y01, fma2(pAz, z01, tA01)));
        const double dA1 = fma2(pAx, x23, fma2(pAy, y23, fma2(pAz, z23, tA23)));
        const double dB0 = fma2(pBx, x01, fma2(pBy, y01, fma2(pBz, z01, tB01)));
        const double dB1 = fma2(pBx, x23, fma2(pBy, y23, fma2(pBz, z23, tB23)));

        float a0, a1, a2, a3, b0, b1, b2, b3;
        unpack2(dA0, a0, a1); unpack2(dA1, a2, a3);
        unpack2(dB0, b0, b1); unpack2(dB1, b2, b3);

        rA0 = fminf(rA0, a0); rA1 = fminf(rA1, a1);
        rA2 = fminf(rA2, a2); rA3 = fminf(rA3, a3);
        rB0 = fminf(rB0, b0); rB1 = fminf(rB1, b1);
        rB2 = fminf(rB2, b2); rB3 = fminf(rB3, b3);

        // col mins over this warp's 64 i's; d''' > 0 so u32-min == float-min
        const unsigned c0 = redux_min_u32(__float_as_uint(fminf(a0, b0)));
        const unsigned c1 = redux_min_u32(__float_as_uint(fminf(a1, b1)));
        const unsigned c2 = redux_min_u32(__float_as_uint(fminf(a2, b2)));
        const unsigned c3 = redux_min_u32(__float_as_uint(fminf(a3, b3)));
        if (lane0)
            colout[k] = make_float4(__uint_as_float(c0), __uint_as_float(c1),
                                    __uint_as_float(c2), __uint_as_float(c3));
    }

    const float rowA = fminf(fminf(rA0, rA1), fminf(rA2, rA3));
    const float rowB = fminf(fminf(rB0, rB1), fminf(rB2, rB3));
    g_rowpart[(b * NPTS + i1) * NJH + jh] = rowA;
    g_rowpart[(b * NPTS + i2) * NJH + jh] = rowB;
}

__device__ __forceinline__ void block_sum_to(float local, int slot) {
    __shared__ float red[8];
#pragma unroll
    for (int o = 16; o; o >>= 1) local += __shfl_down_sync(0xFFFFFFFFu, local, o);
    if ((threadIdx.x & 31) == 0) red[threadIdx.x >> 5] = local;
    __syncthreads();
    if (threadIdx.x == 0) {
        float s = ((red[0] + red[1]) + (red[2] + red[3]))
                + ((red[4] + red[5]) + (red[6] + red[7]));
        g_final[slot] = s;
    }
}

// Stage 2: blocks 0..63 = col side (b, j-slice of 512): min over 64 parts,
// unbias, sum. Blocks 64..71 = row side (b): min over 8 jh, unbias, sum.
__global__ __launch_bounds__(256)
void chamfer_stage2() {
    float local = 0.f;
    if (blockIdx.x < 64) {
        const int b = blockIdx.x >> 3;
        const int j = (blockIdx.x & 7) * 512 + threadIdx.x;   // +0, +256
        float m0 = 1e30f, m1 = 1e30f;
        const float* base = &g_colpart[b * NPART * NPTS];
#pragma unroll 8
        for (int p = 0; p < NPART; p++) {
            m0 = fminf(m0, base[p * NPTS + j]);
            m1 = fminf(m1, base[p * NPTS + j + 256]);
        }
        local = (m0 - BIAS) + (m1 - BIAS);
    } else {
        const int b = blockIdx.x - 64;
        for (int i = threadIdx.x; i < NPTS; i += 256) {
            const float4 v0 = *(const float4*)&g_rowpart[(b * NPTS + i) * NJH];
            const float4 v1 = *(const float4*)&g_rowpart[(b * NPTS + i) * NJH + 4];
            const float m = fminf(fminf(fminf(v0.x, v0.y), fminf(v0.z, v0.w)),
                                  fminf(fminf(v1.x, v1.y), fminf(v1.z, v1.w)));
            local += m - BIAS;
        }
    }
    block_sum_to(local, blockIdx.x);
}

// Stage 3: sum the 72 partials, scale: loss = sum * 0.005 / 32768
__global__ void chamfer_stage3(float* __restrict__ out) {
    __shared__ float red[4];
    float v = (threadIdx.x < 72) ? g_final[threadIdx.x] : 0.f;
#pragma unroll
    for (int o = 16; o; o >>= 1) v += __shfl_down_sync(0xFFFFFFFFu, v, o);
    if ((threadIdx.x & 31) == 0) red[threadIdx.x >> 5] = v;
    __syncthreads();
    if (threadIdx.x == 0) {
        float s = (red[0] + red[1]) + (red[2] + red[3]);
        out[0] = s * (0.005f / 32768.f);
    }
}

extern "C" void kernel_launch(void* const* d_in, const int* in_sizes, int n_in,
                              void* d_out, int out_size) {
    const float* x = (const float*)d_in[0];
    const float* y = (const float*)d_in[1];
    float* out = (float*)d_out;
    chamfer_stage1<<<NB * NIC * NJH, THREADS>>>(x, y);
    chamfer_stage2<<<72, 256>>>();
    chamfer_stage3<<<1, 128>>>(out);
}

// round 7
// speedup vs baseline: 1.4854x; 1.0863x over previous
#include <cuda_runtime.h>

#define NPTS    4096
#define NB      8
#define NIC     16        // i-chunks of 256 queries
#define NJH     16        // j-segments of 256 targets
#define JSEG    256
#define THREADS 128
#define NPART   64        // ic*4 + warp  (64 i's per warp-part)
#define BIAS    128.0f

// stage1 -> stage2 partials (static device arrays: allocation-free)
__device__ float g_colpart[NB * NPART * NPTS];   // [b][part][j], 8.4 MB
__device__ float g_rowpart[NB * NPTS * NJH];     // [b][i][jh],   2 MB
__device__ float g_final[96];

// ---- packed f32x2 + redux helpers ----
__device__ __forceinline__ double pack2(float lo, float hi) {
    double d; asm("mov.b64 %0, {%1, %2};" : "=d"(d) : "f"(lo), "f"(hi)); return d;
}
__device__ __forceinline__ double fma2(double a, double b, double c) {
    double d; asm("fma.rn.f32x2 %0, %1, %2, %3;" : "=d"(d) : "d"(a), "d"(b), "d"(c)); return d;
}
__device__ __forceinline__ double add2(double a, double b) {
    double d; asm("add.rn.f32x2 %0, %1, %2;" : "=d"(d) : "d"(a), "d"(b)); return d;
}
__device__ __forceinline__ void unpack2(double d, float& lo, float& hi) {
    asm("mov.b64 {%0, %1}, %2;" : "=f"(lo), "=f"(hi) : "d"(d));
}
__device__ __forceinline__ void lds_v2b64(double& a, double& b, unsigned addr) {
    asm volatile("ld.shared.v2.b64 {%0, %1}, [%2];" : "=d"(a), "=d"(b) : "r"(addr));
}
__device__ __forceinline__ unsigned redux_min_u32(unsigned v) {
    unsigned r; asm("redux.sync.min.u32 %0, %1, 0xffffffff;" : "=r"(r) : "r"(v)); return r;
}

// Stage 1: block = (b, i-chunk of 256, j-segment of 256). Each pdist tile is
// computed ONCE, biased positive: d''' = |x_i - y_j|^2 + 128, via
//   d''' = (-2qx)tx + (-2qy)ty + (-2qz)tz + ((t^2+128) + q^2)
// Row mins (over j) accumulate in registers (2 queries/thread).
// Col mins (over i) use redux.sync.min.u32 per (warp, j) -> per-part gmem.
// 2048 blocks x 4 warps, 8 blocks/SM resident -> 32 warps/SM.
__global__ __launch_bounds__(THREADS, 8)
void chamfer_stage1(const float* __restrict__ x, const float* __restrict__ y) {
    __shared__ __align__(16) float sm[4 * JSEG];   // planes: tx, ty, tz, t^2+BIAS

    const int blk = blockIdx.x;
    const int jh  = blk & 15;
    const int ic  = (blk >> 4) & 15;
    const int b   = blk >> 8;

    const float* __restrict__ q = x + b * NPTS * 3;
    const float* __restrict__ t = y + b * NPTS * 3;
    const int j0 = jh * JSEG;

    for (int i = threadIdx.x; i < JSEG; i += THREADS) {
        const float tx = t[(j0 + i) * 3 + 0];
        const float ty = t[(j0 + i) * 3 + 1];
        const float tz = t[(j0 + i) * 3 + 2];
        sm[i] = tx; sm[JSEG + i] = ty; sm[2 * JSEG + i] = tz;
        sm[3 * JSEG + i] = tx * tx + ty * ty + tz * tz + BIAS;
    }
    __syncthreads();

    const int i1 = ic * 256 + threadIdx.x;
    const int i2 = i1 + THREADS;
    const float ax = q[i1 * 3 + 0], ay = q[i1 * 3 + 1], az = q[i1 * 3 + 2];
    const float bx = q[i2 * 3 + 0], by = q[i2 * 3 + 1], bz = q[i2 * 3 + 2];

    const double pAx = pack2(-2.f * ax, -2.f * ax);
    const double pAy = pack2(-2.f * ay, -2.f * ay);
    const double pAz = pack2(-2.f * az, -2.f * az);
    const double pBx = pack2(-2.f * bx, -2.f * bx);
    const double pBy = pack2(-2.f * by, -2.f * by);
    const double pBz = pack2(-2.f * bz, -2.f * bz);
    const float qsqA = ax * ax + ay * ay + az * az;
    const float qsqB = bx * bx + by * by + bz * bz;
    const double pQA = pack2(qsqA, qsqA);
    const double pQB = pack2(qsqB, qsqB);

    float rA0 = 1e30f, rA1 = 1e30f, rA2 = 1e30f, rA3 = 1e30f;
    float rB0 = 1e30f, rB1 = 1e30f, rB2 = 1e30f, rB3 = 1e30f;

    const int wid = threadIdx.x >> 5;
    const bool lane0 = (threadIdx.x & 31) == 0;
    float4* __restrict__ colout =
        (float4*)&g_colpart[(b * NPART + ic * 4 + wid) * NPTS + j0];

    unsigned a = (unsigned)__cvta_generic_to_shared(sm);

#pragma unroll 4
    for (int k = 0; k < JSEG / 4; k++, a += 16) {
        double x01, x23, y01, y23, z01, z23, w01, w23;
        lds_v2b64(x01, x23, a);
        lds_v2b64(y01, y23, a + 1024u);
        lds_v2b64(z01, z23, a + 2048u);
        lds_v2b64(w01, w23, a + 3072u);

        const double tA01 = add2(w01, pQA), tA23 = add2(w23, pQA);
        const double tB01 = add2(w01, pQB), tB23 = add2(w23, pQB);

        const double dA0 = fma2(pAx, x01, fma2(pAy, y01, fma2(pAz, z01, tA01)));
        const double dA1 = fma2(pAx, x23, fma2(pAy, y23, fma2(pAz, z23, tA23)));
        const double dB0 = fma2(pBx, x01, fma2(pBy, y01, fma2(pBz, z01, tB01)));
        const double dB1 = fma2(pBx, x23, fma2(pBy, y23, fma2(pBz, z23, tB23)));

        float a0, a1, a2, a3, b0, b1, b2, b3;
        unpack2(dA0, a0, a1); unpack2(dA1, a2, a3);
        unpack2(dB0, b0, b1); unpack2(dB1, b2, b3);

        rA0 = fminf(rA0, a0); rA1 = fminf(rA1, a1);
        rA2 = fminf(rA2, a2); rA3 = fminf(rA3, a3);
        rB0 = fminf(rB0, b0); rB1 = fminf(rB1, b1);
        rB2 = fminf(rB2, b2); rB3 = fminf(rB3, b3);

        // col mins over this warp's 64 i's; d''' > 0 so u32-min == float-min
        const unsigned c0 = redux_min_u32(__float_as_uint(fminf(a0, b0)));
        const unsigned c1 = redux_min_u32(__float_as_uint(fminf(a1, b1)));
        const unsigned c2 = redux_min_u32(__float_as_uint(fminf(a2, b2)));
        const unsigned c3 = redux_min_u32(__float_as_uint(fminf(a3, b3)));
        if (lane0)
            colout[k] = make_float4(__uint_as_float(c0), __uint_as_float(c1),
                                    __uint_as_float(c2), __uint_as_float(c3));
    }

    const float rowA = fminf(fminf(rA0, rA1), fminf(rA2, rA3));
    const float rowB = fminf(fminf(rB0, rB1), fminf(rB2, rB3));
    g_rowpart[(b * NPTS + i1) * NJH + jh] = rowA;
    g_rowpart[(b * NPTS + i2) * NJH + jh] = rowB;
}

__device__ __forceinline__ void block_sum_to(float local, int slot) {
    __shared__ float red[8];
#pragma unroll
    for (int o = 16; o; o >>= 1) local += __shfl_down_sync(0xFFFFFFFFu, local, o);
    if ((threadIdx.x & 31) == 0) red[threadIdx.x >> 5] = local;
    __syncthreads();
    if (threadIdx.x == 0) {
        float s = ((red[0] + red[1]) + (red[2] + red[3]))
                + ((red[4] + red[5]) + (red[6] + red[7]));
        g_final[slot] = s;
    }
}

// Stage 2: blocks 0..63 = col side (b, j-slice of 512): min over 64 parts,
// unbias, sum. Blocks 64..79 = row side (b, i-half): min over 16 jh, unbias, sum.
__global__ __launch_bounds__(256)
void chamfer_stage2() {
    float local = 0.f;
    if (blockIdx.x < 64) {
        const int b = blockIdx.x >> 3;
        const int j = (blockIdx.x & 7) * 512 + threadIdx.x;   // +0, +256
        float m0 = 1e30f, m1 = 1e30f;
        const float* base = &g_colpart[b * NPART * NPTS];
#pragma unroll 8
        for (int p = 0; p < NPART; p++) {
            m0 = fminf(m0, base[p * NPTS + j]);
            m1 = fminf(m1, base[p * NPTS + j + 256]);
        }
        local = (m0 - BIAS) + (m1 - BIAS);
    } else {
        const int blk2 = blockIdx.x - 64;   // 0..15
        const int b = blk2 >> 1;
        const int ibase = (blk2 & 1) * 2048;
        for (int i = ibase + threadIdx.x; i < ibase + 2048; i += 256) {
            const float4* r = (const float4*)&g_rowpart[(b * NPTS + i) * NJH];
            const float4 v0 = r[0], v1 = r[1], v2 = r[2], v3 = r[3];
            float m = fminf(fminf(fminf(v0.x, v0.y), fminf(v0.z, v0.w)),
                            fminf(fminf(v1.x, v1.y), fminf(v1.z, v1.w)));
            m = fminf(m, fminf(fminf(fminf(v2.x, v2.y), fminf(v2.z, v2.w)),
                               fminf(fminf(v3.x, v3.y), fminf(v3.z, v3.w))));
            local += m - BIAS;
        }
    }
    block_sum_to(local, blockIdx.x);
}

// Stage 3: sum the 80 partials, scale: loss = sum * 0.005 / 32768
__global__ void chamfer_stage3(float* __restrict__ out) {
    __shared__ float red[4];
    float v = (threadIdx.x < 80) ? g_final[threadIdx.x] : 0.f;
#pragma unroll
    for (int o = 16; o; o >>= 1) v += __shfl_down_sync(0xFFFFFFFFu, v, o);
    if ((threadIdx.x & 31) == 0) red[threadIdx.x >> 5] = v;
    __syncthreads();
    if (threadIdx.x == 0) {
        float s = (red[0] + red[1]) + (red[2] + red[3]);
        out[0] = s * (0.005f / 32768.f);
    }
}

extern "C" void kernel_launch(void* const* d_in, const int* in_sizes, int n_in,
                              void* d_out, int out_size) {
    const float* x = (const float*)d_in[0];
    const float* y = (const float*)d_in[1];
    float* out = (float*)d_out;
    chamfer_stage1<<<NB * NIC * NJH, THREADS>>>(x, y);
    chamfer_stage2<<<80, 256>>>();
    chamfer_stage3<<<1, 128>>>(out);
}